// round 8
// baseline (speedup 1.0000x reference)
#include <cuda_runtime.h>
#include <cuda_fp16.h>
#include <cstdint>

// FastRP link prediction, dedup two-phase with fp16 emb table:
//   1) clear byte-flags + softmax weights
//   2) mark referenced nodes (byte scatter)
//   3) build emb16[node] (fp16) only for marked nodes, ascending node order
//   4) gather: TWO threads per edge (pair-lane), 8 LDG.128 each, shfl exchange
// Unique-node read floor: ~137.7k nodes * 3072 B = ~423 MB (build is at it).

#define P_PATHS 4
#define K_POWERS 3
#define PK 12
#define DIM 64
#define NMAX 250000

__device__ unsigned char g_flags[NMAX];                 // 250 KB
__device__ uint4         g_emb16[(size_t)NMAX * 8];     // 32 MB (64 halves/node)
__device__ float         g_w[PK];

// ---------------- kernel 1: clear flags + softmax weights ----------------
__global__ __launch_bounds__(256) void clear_kernel(const float* __restrict__ fw, int N)
{
    int i = blockIdx.x * blockDim.x + threadIdx.x;
    int n4 = (N + 3) >> 2;
    if (i < n4) ((uint32_t*)g_flags)[i] = 0;
    if (i == 0) {
        #pragma unroll
        for (int p = 0; p < P_PATHS; p++) {
            float a = fw[p * K_POWERS + 0];
            float b = fw[p * K_POWERS + 1];
            float c = fw[p * K_POWERS + 2];
            float m = fmaxf(a, fmaxf(b, c));
            float ea = __expf(a - m);
            float eb = __expf(b - m);
            float ec = __expf(c - m);
            float inv = 1.0f / (ea + eb + ec);
            g_w[p * K_POWERS + 0] = ea * inv;
            g_w[p * K_POWERS + 1] = eb * inv;
            g_w[p * K_POWERS + 2] = ec * inv;
        }
    }
}

// ---------------- kernel 2: mark referenced nodes ----------------
__global__ __launch_bounds__(256) void mark_kernel(
    const int* __restrict__ idx_i, const int* __restrict__ idx_j, int E)
{
    int r = blockIdx.x * blockDim.x + threadIdx.x;
    if (r < E)          g_flags[__ldg(idx_i + r)] = 1;
    else if (r < 2 * E) g_flags[__ldg(idx_j + r - E)] = 1;
}

// ---------------- kernel 3: build fp16 emb for marked nodes ---------------
// 16 threads per node, each owns one float4 (4 dims) -> 4 halves (uint2).
__global__ __launch_bounds__(256) void build_kernel(
    const float* __restrict__ feats, int N)
{
    const int node = (blockIdx.x * blockDim.x + threadIdx.x) >> 4;
    if (node >= N) return;
    if (!g_flags[node]) return;   // uniform per 16-thread group

    const int l = threadIdx.x & 15;

    float w[PK];
    #pragma unroll
    for (int pk = 0; pk < PK; pk++) w[pk] = g_w[pk];

    const float4* __restrict__ f4 = (const float4*)feats;
    const int base = node * 16 + l;
    const int stride16 = N * 16;

    float ax = 0.f, ay = 0.f, az = 0.f, aw = 0.f;
    #pragma unroll
    for (int pk = 0; pk < PK; pk++) {
        float4 v = __ldg(f4 + pk * stride16 + base);
        ax = fmaf(w[pk], v.x, ax);
        ay = fmaf(w[pk], v.y, ay);
        az = fmaf(w[pk], v.z, az);
        aw = fmaf(w[pk], v.w, aw);
    }

    __half2 h0 = __floats2half2_rn(ax, ay);
    __half2 h1 = __floats2half2_rn(az, aw);
    uint2 packed;
    packed.x = *reinterpret_cast<uint32_t*>(&h0);
    packed.y = *reinterpret_cast<uint32_t*>(&h1);
    ((uint2*)g_emb16)[base] = packed;   // half-warp writes 128B contiguous
}

// ---------------- kernel 4: gather + score (pair-lane, 2 threads/edge) ----
// Even lane loads emb16[i] (8x uint4), odd lane loads emb16[j].
// Exchange the half each partner needs via shfl_xor(1): even keeps its v[0..3]
// (a-lo) and receives partner's v[0..3] (b-lo); odd keeps v[4..7] (b-hi) and
// receives partner's v[4..7] (a-hi). Each lane scores 32 dims; one shfl-add.
__global__ __launch_bounds__(256) void gather_kernel(
    const float* __restrict__ intercept,
    const int* __restrict__ idx_i, const int* __restrict__ idx_j,
    float* __restrict__ out, int E)
{
    const int t = blockIdx.x * blockDim.x + threadIdx.x;
    int edge = t >> 1;
    const int par  = t & 1;              // 0 -> node i, 1 -> node j
    const bool valid = (edge < E);
    if (edge >= E) edge = E - 1;         // keep lanes converged for shfl

    const int node = par ? __ldg(idx_j + edge) : __ldg(idx_i + edge);
    const uint4* __restrict__ p = g_emb16 + (size_t)node * 8;

    uint4 v[8];
    #pragma unroll
    for (int c = 0; c < 8; c++) v[c] = __ldg(p + c);

    // Exchange 4 uint4: each lane sends the half IT doesn't score.
    // Even scores dims 0..31 (chunks 0..3): has a[0..3], needs b[0..3].
    // Odd  scores dims 32..63 (chunks 4..7): has b[4..7], needs a[4..7].
    const unsigned FULL = 0xffffffffu;
    uint4 o[4];
    #pragma unroll
    for (int c = 0; c < 4; c++) {
        // even sends v[c] (a-lo, which odd does NOT need) -- wait: odd needs a-hi.
        // send rule: even sends v[c+4] (a-hi), odd sends v[c] (b-lo).
        uint4 snd = par ? v[c] : v[c + 4];
        o[c].x = __shfl_xor_sync(FULL, snd.x, 1);
        o[c].y = __shfl_xor_sync(FULL, snd.y, 1);
        o[c].z = __shfl_xor_sync(FULL, snd.z, 1);
        o[c].w = __shfl_xor_sync(FULL, snd.w, 1);
        // even receives odd's v[c]   = b[c]    (b-lo)  ✓
        // odd  receives even's v[c+4]= a[c+4]  (a-hi)  ✓
    }

    // Select this lane's own half: even uses v[0..3], odd uses v[4..7].
    float s = 0.f;
    #pragma unroll
    for (int c = 0; c < 4; c++) {
        uint4 mine = par ? v[c + 4] : v[c];
        const uint32_t* um = reinterpret_cast<const uint32_t*>(&mine);
        const uint32_t* uo = reinterpret_cast<const uint32_t*>(&o[c]);
        #pragma unroll
        for (int q = 0; q < 4; q++) {
            __half2 hm = *reinterpret_cast<const __half2*>(&um[q]);
            __half2 ho = *reinterpret_cast<const __half2*>(&uo[q]);
            __half2 d = __hsub2(hm, ho);
            float2 f = __half22float2(d);
            s = fmaf(f.x, f.x, s);
            s = fmaf(f.y, f.y, s);
        }
    }

    // Combine the two lanes' partial sums.
    s += __shfl_xor_sync(FULL, s, 1);

    if (valid && par == 0) {
        float logit = __ldg(intercept) - s * (1.0f / (float)DIM);
        out[edge] = 1.0f / (1.0f + __expf(-logit));
    }
}

// ---------------- fallback: direct per-edge gather (proven R3 kernel) -----
__global__ __launch_bounds__(256) void fastrp_edge_kernel(
    const float* __restrict__ feats, const float* __restrict__ fw,
    const float* __restrict__ intercept,
    const int* __restrict__ idx_i, const int* __restrict__ idx_j,
    float* __restrict__ out, int E, int N)
{
    const int gwarp = (blockIdx.x * blockDim.x + threadIdx.x) >> 5;
    const int lane  = threadIdx.x & 31;
    if (gwarp >= E) return;

    float w[PK];
    #pragma unroll
    for (int p = 0; p < P_PATHS; p++) {
        float a = __ldg(fw + p * K_POWERS + 0);
        float b = __ldg(fw + p * K_POWERS + 1);
        float c = __ldg(fw + p * K_POWERS + 2);
        float m = fmaxf(a, fmaxf(b, c));
        float ea = __expf(a - m), eb = __expf(b - m), ec = __expf(c - m);
        float inv = 1.0f / (ea + eb + ec);
        w[p * K_POWERS + 0] = ea * inv;
        w[p * K_POWERS + 1] = eb * inv;
        w[p * K_POWERS + 2] = ec * inv;
    }

    const int ni = __ldg(idx_i + gwarp);
    const int nj = __ldg(idx_j + gwarp);
    const long long node = (lane < 16) ? (long long)ni : (long long)nj;
    const int d4 = lane & 15;

    const float4* __restrict__ f4 = (const float4*)feats;
    const long long nodebase = node * 16 + d4;
    const long long stride16 = (long long)N * 16;

    float ax = 0.f, ay = 0.f, az = 0.f, aw = 0.f;
    #pragma unroll
    for (int pk = 0; pk < PK; pk++) {
        float4 v = __ldg(f4 + (long long)pk * stride16 + nodebase);
        ax = fmaf(w[pk], v.x, ax);
        ay = fmaf(w[pk], v.y, ay);
        az = fmaf(w[pk], v.z, az);
        aw = fmaf(w[pk], v.w, aw);
    }

    const unsigned FULL = 0xffffffffu;
    float dx = ax - __shfl_xor_sync(FULL, ax, 16);
    float dy = ay - __shfl_xor_sync(FULL, ay, 16);
    float dz = az - __shfl_xor_sync(FULL, az, 16);
    float dw = aw - __shfl_xor_sync(FULL, aw, 16);
    float s = dx * dx + dy * dy + dz * dz + dw * dw;

    #pragma unroll
    for (int off = 8; off >= 1; off >>= 1)
        s += __shfl_xor_sync(FULL, s, off);

    if (lane == 0) {
        float logit = __ldg(intercept) - s * (1.0f / (float)DIM);
        out[gwarp] = 1.0f / (1.0f + __expf(-logit));
    }
}

extern "C" void kernel_launch(void* const* d_in, const int* in_sizes, int n_in,
                              void* d_out, int out_size)
{
    const float* feats     = (const float*)d_in[0];
    const float* fw        = (const float*)d_in[1];
    const float* intercept = (const float*)d_in[2];
    const int*   idx_i     = (const int*)d_in[3];
    const int*   idx_j     = (const int*)d_in[4];
    float*       out       = (float*)d_out;

    const int E = in_sizes[3];
    const int N = in_sizes[0] / (PK * DIM);

    if (N <= NMAX) {
        clear_kernel<<<(((N + 3) / 4) + 255) / 256, 256>>>(fw, N);
        mark_kernel<<<(2 * E + 255) / 256, 256>>>(idx_i, idx_j, E);
        build_kernel<<<(N * 16 + 255) / 256, 256>>>(feats, N);
        gather_kernel<<<(2 * E + 255) / 256, 256>>>(intercept, idx_i, idx_j, out, E);
    } else {
        const int blocks = (E + 7) / 8;
        fastrp_edge_kernel<<<blocks, 256>>>(feats, fw, intercept, idx_i, idx_j, out, E, N);
    }
}

// round 9
// speedup vs baseline: 1.0193x; 1.0193x over previous
#include <cuda_runtime.h>
#include <cuda_fp16.h>
#include <cstdint>

// FastRP link prediction, dedup two-phase with fp16 emb table:
//   1) clear byte-flags + softmax weights
//   2) mark referenced nodes (byte scatter)
//   3) build emb16[node] (fp16) only for marked nodes, ascending node order
//   4) gather v3: 8 lanes per node, 1 wavefront per node-read, MLP=4.
// Build is at the unique-node read floor (~423 MB). Gather now sized for the
// L1tex wavefront queue: 1 line-touch per node instead of 8.

#define P_PATHS 4
#define K_POWERS 3
#define PK 12
#define DIM 64
#define NMAX 250000

__device__ unsigned char g_flags[NMAX];                 // 250 KB
__device__ uint4         g_emb16[(size_t)NMAX * 8];     // 32 MB (64 halves/node)
__device__ float         g_w[PK];

// ---------------- kernel 1: clear flags + softmax weights ----------------
__global__ __launch_bounds__(256) void clear_kernel(const float* __restrict__ fw, int N)
{
    int i = blockIdx.x * blockDim.x + threadIdx.x;
    int n4 = (N + 3) >> 2;
    if (i < n4) ((uint32_t*)g_flags)[i] = 0;
    if (i == 0) {
        #pragma unroll
        for (int p = 0; p < P_PATHS; p++) {
            float a = fw[p * K_POWERS + 0];
            float b = fw[p * K_POWERS + 1];
            float c = fw[p * K_POWERS + 2];
            float m = fmaxf(a, fmaxf(b, c));
            float ea = __expf(a - m);
            float eb = __expf(b - m);
            float ec = __expf(c - m);
            float inv = 1.0f / (ea + eb + ec);
            g_w[p * K_POWERS + 0] = ea * inv;
            g_w[p * K_POWERS + 1] = eb * inv;
            g_w[p * K_POWERS + 2] = ec * inv;
        }
    }
}

// ---------------- kernel 2: mark referenced nodes ----------------
__global__ __launch_bounds__(256) void mark_kernel(
    const int* __restrict__ idx_i, const int* __restrict__ idx_j, int E)
{
    int r = blockIdx.x * blockDim.x + threadIdx.x;
    if (r < E)          g_flags[__ldg(idx_i + r)] = 1;
    else if (r < 2 * E) g_flags[__ldg(idx_j + r - E)] = 1;
}

// ---------------- kernel 3: build fp16 emb for marked nodes ---------------
// 16 threads per node, each owns one float4 (4 dims) -> 4 halves (uint2).
__global__ __launch_bounds__(256) void build_kernel(
    const float* __restrict__ feats, int N)
{
    const int node = (blockIdx.x * blockDim.x + threadIdx.x) >> 4;
    if (node >= N) return;
    if (!g_flags[node]) return;   // uniform per 16-thread group

    const int l = threadIdx.x & 15;

    float w[PK];
    #pragma unroll
    for (int pk = 0; pk < PK; pk++) w[pk] = g_w[pk];

    const float4* __restrict__ f4 = (const float4*)feats;
    const int base = node * 16 + l;
    const int stride16 = N * 16;

    float ax = 0.f, ay = 0.f, az = 0.f, aw = 0.f;
    #pragma unroll
    for (int pk = 0; pk < PK; pk++) {
        float4 v = __ldg(f4 + pk * stride16 + base);
        ax = fmaf(w[pk], v.x, ax);
        ay = fmaf(w[pk], v.y, ay);
        az = fmaf(w[pk], v.z, az);
        aw = fmaf(w[pk], v.w, aw);
    }

    __half2 h0 = __floats2half2_rn(ax, ay);
    __half2 h1 = __floats2half2_rn(az, aw);
    uint2 packed;
    packed.x = *reinterpret_cast<uint32_t*>(&h0);
    packed.y = *reinterpret_cast<uint32_t*>(&h1);
    ((uint2*)g_emb16)[base] = packed;   // half-warp writes 128B contiguous
}

// ---------------- kernel 4: gather v3 --------------------------------------
// Lane layout: pair = lane>>4 (which of 2 edges this step), half = (lane>>3)&1
// (0 -> node i, 1 -> node j), sub = lane&7 (which uint4 of the node's 128B).
// One warp LDG instruction covers 4 node records = 4 lines = 4 wavefronts.
// Each warp processes STEPS*2 edges; all STEPS loads issued up-front (MLP=4).
#define GSTEPS 4
__global__ __launch_bounds__(256) void gather_kernel(
    const float* __restrict__ intercept,
    const int* __restrict__ idx_i, const int* __restrict__ idx_j,
    float* __restrict__ out, int E)
{
    const int tid   = blockIdx.x * blockDim.x + threadIdx.x;
    const int warp  = tid >> 5;
    const int lane  = threadIdx.x & 31;
    const int pair  = lane >> 4;
    const int half  = (lane >> 3) & 1;
    const int sub   = lane & 7;

    const int ebase = warp * (2 * GSTEPS);
    if (ebase >= E) return;

    const unsigned FULL = 0xffffffffu;

    // Issue all loads first (independent -> MLP = GSTEPS).
    uint4 v[GSTEPS];
    int   evalid[GSTEPS];
    #pragma unroll
    for (int s = 0; s < GSTEPS; s++) {
        int e = ebase + s * 2 + pair;
        evalid[s] = (e < E);
        int ec = evalid[s] ? e : (E - 1);          // clamp, keep lanes converged
        int node = half ? __ldg(idx_j + ec) : __ldg(idx_i + ec);
        v[s] = __ldg(g_emb16 + node * 8 + sub);    // 8 lanes span the 128B record
    }

    float inter = __ldg(intercept);

    #pragma unroll
    for (int s = 0; s < GSTEPS; s++) {
        // Partner half's uint4 (same edge, same sub, other node).
        uint4 o;
        o.x = __shfl_xor_sync(FULL, v[s].x, 8);
        o.y = __shfl_xor_sync(FULL, v[s].y, 8);
        o.z = __shfl_xor_sync(FULL, v[s].z, 8);
        o.w = __shfl_xor_sync(FULL, v[s].w, 8);

        const uint32_t* um = reinterpret_cast<const uint32_t*>(&v[s]);
        const uint32_t* uo = reinterpret_cast<const uint32_t*>(&o);
        float sacc = 0.f;
        #pragma unroll
        for (int q = 0; q < 4; q++) {
            __half2 hm = *reinterpret_cast<const __half2*>(&um[q]);
            __half2 ho = *reinterpret_cast<const __half2*>(&uo[q]);
            __half2 d = __hsub2(hm, ho);
            float2 f = __half22float2(d);
            sacc = fmaf(f.x, f.x, sacc);
            sacc = fmaf(f.y, f.y, sacc);
        }

        // Reduce over the 8 sub-lanes (stay within the 8-lane group).
        sacc += __shfl_xor_sync(FULL, sacc, 1);
        sacc += __shfl_xor_sync(FULL, sacc, 2);
        sacc += __shfl_xor_sync(FULL, sacc, 4);

        if (half == 0 && sub == 0 && evalid[s]) {
            int e = ebase + s * 2 + pair;
            float logit = inter - sacc * (1.0f / (float)DIM);
            out[e] = 1.0f / (1.0f + __expf(-logit));
        }
    }
}

// ---------------- fallback: direct per-edge gather (proven R3 kernel) -----
__global__ __launch_bounds__(256) void fastrp_edge_kernel(
    const float* __restrict__ feats, const float* __restrict__ fw,
    const float* __restrict__ intercept,
    const int* __restrict__ idx_i, const int* __restrict__ idx_j,
    float* __restrict__ out, int E, int N)
{
    const int gwarp = (blockIdx.x * blockDim.x + threadIdx.x) >> 5;
    const int lane  = threadIdx.x & 31;
    if (gwarp >= E) return;

    float w[PK];
    #pragma unroll
    for (int p = 0; p < P_PATHS; p++) {
        float a = __ldg(fw + p * K_POWERS + 0);
        float b = __ldg(fw + p * K_POWERS + 1);
        float c = __ldg(fw + p * K_POWERS + 2);
        float m = fmaxf(a, fmaxf(b, c));
        float ea = __expf(a - m), eb = __expf(b - m), ec = __expf(c - m);
        float inv = 1.0f / (ea + eb + ec);
        w[p * K_POWERS + 0] = ea * inv;
        w[p * K_POWERS + 1] = eb * inv;
        w[p * K_POWERS + 2] = ec * inv;
    }

    const int ni = __ldg(idx_i + gwarp);
    const int nj = __ldg(idx_j + gwarp);
    const long long node = (lane < 16) ? (long long)ni : (long long)nj;
    const int d4 = lane & 15;

    const float4* __restrict__ f4 = (const float4*)feats;
    const long long nodebase = node * 16 + d4;
    const long long stride16 = (long long)N * 16;

    float ax = 0.f, ay = 0.f, az = 0.f, aw = 0.f;
    #pragma unroll
    for (int pk = 0; pk < PK; pk++) {
        float4 v = __ldg(f4 + (long long)pk * stride16 + nodebase);
        ax = fmaf(w[pk], v.x, ax);
        ay = fmaf(w[pk], v.y, ay);
        az = fmaf(w[pk], v.z, az);
        aw = fmaf(w[pk], v.w, aw);
    }

    const unsigned FULL = 0xffffffffu;
    float dx = ax - __shfl_xor_sync(FULL, ax, 16);
    float dy = ay - __shfl_xor_sync(FULL, ay, 16);
    float dz = az - __shfl_xor_sync(FULL, az, 16);
    float dw = aw - __shfl_xor_sync(FULL, aw, 16);
    float s = dx * dx + dy * dy + dz * dz + dw * dw;

    #pragma unroll
    for (int off = 8; off >= 1; off >>= 1)
        s += __shfl_xor_sync(FULL, s, off);

    if (lane == 0) {
        float logit = __ldg(intercept) - s * (1.0f / (float)DIM);
        out[gwarp] = 1.0f / (1.0f + __expf(-logit));
    }
}

extern "C" void kernel_launch(void* const* d_in, const int* in_sizes, int n_in,
                              void* d_out, int out_size)
{
    const float* feats     = (const float*)d_in[0];
    const float* fw        = (const float*)d_in[1];
    const float* intercept = (const float*)d_in[2];
    const int*   idx_i     = (const int*)d_in[3];
    const int*   idx_j     = (const int*)d_in[4];
    float*       out       = (float*)d_out;

    const int E = in_sizes[3];
    const int N = in_sizes[0] / (PK * DIM);

    if (N <= NMAX) {
        clear_kernel<<<(((N + 3) / 4) + 255) / 256, 256>>>(fw, N);
        mark_kernel<<<(2 * E + 255) / 256, 256>>>(idx_i, idx_j, E);
        build_kernel<<<(N * 16 + 255) / 256, 256>>>(feats, N);
        // one warp handles 2*GSTEPS edges
        int warps_needed = (E + 2 * GSTEPS - 1) / (2 * GSTEPS);
        int blocks = (warps_needed * 32 + 255) / 256;
        gather_kernel<<<blocks, 256>>>(intercept, idx_i, idx_j, out, E);
    } else {
        const int blocks = (E + 7) / 8;
        fastrp_edge_kernel<<<blocks, 256>>>(feats, fw, intercept, idx_i, idx_j, out, E, N);
    }
}